// round 14
// baseline (speedup 1.0000x reference)
#include <cuda_runtime.h>

// B3-spline à-trous UWT, LEVEL=3.  x:(8,1024,1024) f32 -> (8,4,1024,1024) f32
// Phase 1: horizontal 5-tap straight from gmem (overlap absorbed by L1) -> smem.
// Phase 2: center prefetch first, then 4 independent vertical 5-tap items/thread.
// Single __syncthreads per block. Streaming stores for write-once planes.

#define IMG_H 1024
#define IMG_W 1024
#define NBATCH 8
#define PLANE (IMG_H * IMG_W)
#define W4 (IMG_W / 4)

__device__ float g_scratch1[NBATCH * PLANE];
__device__ float g_scratch2[NBATCH * PLANE];

__device__ __forceinline__ int reflect_i(int i, int n) {
    return i < 0 ? -i : (i >= n ? 2 * n - 2 - i : i);
}

template <int D, bool LAST>
__global__ __launch_bounds__(256, 6) void uwt_level_kernel(
    const float* __restrict__ cin,
    float* __restrict__ wout,
    float* __restrict__ cout)
{
    constexpr int TX = 64, TY = 64;
    constexpr int SH = TY + 4 * D;          // h-conv rows needed (68, 72, 80)
    constexpr int PITCH = 68;               // floats

    __shared__ __align__(16) float s1[SH][PITCH];

    const int tid = threadIdx.x;            // 0..255
    const int b   = blockIdx.z;
    const int x0  = blockIdx.x * TX;
    const int y0  = blockIdx.y * TY;

    const float* in = cin + b * PLANE;      // 32-bit offset ok (8M max)
    const bool xint = (x0 >= 8) && (x0 + TX + 8 <= IMG_W);
    const int xb4 = x0 >> 2;

    // ============ phase 1: horizontal 5-tap, gmem -> smem ============
    constexpr int ITEMS1 = SH * 16;
    constexpr int IT1 = (ITEMS1 + 255) / 256;
    #pragma unroll
    for (int t = 0; t < IT1; t++) {
        const int i = tid + t * 256;
        if (IT1 * 256 == ITEMS1 || i < ITEMS1) {
            const int rr = i >> 4;
            const int oc = i & 15;
            const int gy = reflect_i(y0 - 2 * D + rr, IMG_H);
            const float* rp = in + gy * IMG_W;
            float4 v;
            if (xint) {
                const float4* rp4 = (const float4*)rp;
                if constexpr (D == 4) {
                    float4 A0 = rp4[xb4 + oc - 2];
                    float4 A1 = rp4[xb4 + oc - 1];
                    float4 A2 = rp4[xb4 + oc    ];
                    float4 A3 = rp4[xb4 + oc + 1];
                    float4 A4 = rp4[xb4 + oc + 2];
                    v.x = 0.0625f * (A0.x + A4.x) + 0.25f * (A1.x + A3.x) + 0.375f * A2.x;
                    v.y = 0.0625f * (A0.y + A4.y) + 0.25f * (A1.y + A3.y) + 0.375f * A2.y;
                    v.z = 0.0625f * (A0.z + A4.z) + 0.25f * (A1.z + A3.z) + 0.375f * A2.z;
                    v.w = 0.0625f * (A0.w + A4.w) + 0.25f * (A1.w + A3.w) + 0.375f * A2.w;
                } else {
                    float4 B0 = rp4[xb4 + oc - 1];
                    float4 B1 = rp4[xb4 + oc    ];
                    float4 B2 = rp4[xb4 + oc + 1];
                    float f[12] = {B0.x, B0.y, B0.z, B0.w,
                                   B1.x, B1.y, B1.z, B1.w,
                                   B2.x, B2.y, B2.z, B2.w};
                    v.x = 0.0625f * (f[4 - 2*D] + f[4 + 2*D]) + 0.25f * (f[4 - D] + f[4 + D]) + 0.375f * f[4];
                    v.y = 0.0625f * (f[5 - 2*D] + f[5 + 2*D]) + 0.25f * (f[5 - D] + f[5 + D]) + 0.375f * f[5];
                    v.z = 0.0625f * (f[6 - 2*D] + f[6 + 2*D]) + 0.25f * (f[6 - D] + f[6 + D]) + 0.375f * f[6];
                    v.w = 0.0625f * (f[7 - 2*D] + f[7 + 2*D]) + 0.25f * (f[7 - D] + f[7 + D]) + 0.375f * f[7];
                }
            } else {
                const int xl = x0 + oc * 4;
                float o[4];
                #pragma unroll
                for (int n = 0; n < 4; n++) {
                    float a0 = rp[reflect_i(xl + n - 2 * D, IMG_W)];
                    float a1 = rp[reflect_i(xl + n -     D, IMG_W)];
                    float a2 = rp[reflect_i(xl + n,         IMG_W)];
                    float a3 = rp[reflect_i(xl + n +     D, IMG_W)];
                    float a4 = rp[reflect_i(xl + n + 2 * D, IMG_W)];
                    o[n] = 0.0625f * (a0 + a4) + 0.25f * (a1 + a3) + 0.375f * a2;
                }
                v = make_float4(o[0], o[1], o[2], o[3]);
            }
            *(float4*)&s1[rr][oc * 4] = v;
        }
    }

    // -------- prefetch center values (independent of smem) --------
    const int col = tid & 15;               // f4 column 0..15
    const int r0  = tid >> 4;               // base row 0..15; items at r0+16k
    const float4* in4 = (const float4*)in;
    int go[4];
    float4 cc[4];
    #pragma unroll
    for (int k = 0; k < 4; k++) {
        go[k] = (y0 + r0 + 16 * k) * W4 + xb4 + col;
        cc[k] = in4[go[k]];
    }

    __syncthreads();

    // ============ phase 2: vertical 5-tap from smem ============
    float4* wo = (float4*)(wout + b * 4 * PLANE);
    float4* co = (float4*)(cout + b * (LAST ? 4 : 1) * PLANE);

    #pragma unroll
    for (int k = 0; k < 4; k++) {
        const int r = r0 + 16 * k;          // tile row; s1 rows r .. r+4D
        float4 a0 = *(const float4*)&s1[r        ][col * 4];
        float4 a1 = *(const float4*)&s1[r +     D][col * 4];
        float4 a2 = *(const float4*)&s1[r + 2 * D][col * 4];
        float4 a3 = *(const float4*)&s1[r + 3 * D][col * 4];
        float4 a4 = *(const float4*)&s1[r + 4 * D][col * 4];
        float4 v;
        v.x = 0.0625f * (a0.x + a4.x) + 0.25f * (a1.x + a3.x) + 0.375f * a2.x;
        v.y = 0.0625f * (a0.y + a4.y) + 0.25f * (a1.y + a3.y) + 0.375f * a2.y;
        v.z = 0.0625f * (a0.z + a4.z) + 0.25f * (a1.z + a3.z) + 0.375f * a2.z;
        v.w = 0.0625f * (a0.w + a4.w) + 0.25f * (a1.w + a3.w) + 0.375f * a2.w;

        float4 w4 = make_float4(cc[k].x - v.x, cc[k].y - v.y,
                                cc[k].z - v.z, cc[k].w - v.w);
        __stcs(&wo[go[k]], w4);             // w: write-once, evict-first
        if constexpr (LAST)
            __stcs(&co[go[k]], v);          // c3: write-once too
        else
            co[go[k]] = v;                  // c_next: re-read by next level
    }
}

extern "C" void kernel_launch(void* const* d_in, const int* in_sizes, int n_in,
                              void* d_out, int out_size)
{
    (void)in_sizes; (void)n_in; (void)out_size;
    const float* x = (const float*)d_in[0];
    float* out = (float*)d_out;

    float *c1, *c2;
    cudaGetSymbolAddress((void**)&c1, g_scratch1);
    cudaGetSymbolAddress((void**)&c2, g_scratch2);

    dim3 block(256, 1, 1);
    dim3 grid(IMG_W / 64, IMG_H / 64, NBATCH);

    // Note: wout indexes with batch stride 4*PLANE internally; cout stride is
    // PLANE for scratch (LAST=false) and 4*PLANE for the final level.
    uwt_level_kernel<1, false><<<grid, block>>>(x,  out + 0L * PLANE, c1);
    uwt_level_kernel<2, false><<<grid, block>>>(c1, out + 1L * PLANE, c2);
    uwt_level_kernel<4, true ><<<grid, block>>>(c2, out + 2L * PLANE,
                                                    out + 3L * PLANE);
}

// round 15
// speedup vs baseline: 1.0089x; 1.0089x over previous
#include <cuda_runtime.h>

// B3-spline à-trous UWT, LEVEL=3.  x:(8,1024,1024) f32 -> (8,4,1024,1024) f32
// Phase 1: horizontal 5-tap straight from gmem (overlap absorbed by L1) -> smem.
// Phase 2: center prefetch first, then 4 independent vertical 5-tap items/thread.
// Single __syncthreads per block. Streaming stores for write-once planes.

#define IMG_H 1024
#define IMG_W 1024
#define NBATCH 8
#define PLANE (IMG_H * IMG_W)
#define W4 (IMG_W / 4)

__device__ float g_scratch1[NBATCH * PLANE];
__device__ float g_scratch2[NBATCH * PLANE];

__device__ __forceinline__ int reflect_i(int i, int n) {
    return i < 0 ? -i : (i >= n ? 2 * n - 2 - i : i);
}

template <int D, bool LAST>
__global__ __launch_bounds__(256, 6) void uwt_level_kernel(
    const float* __restrict__ cin,
    float* __restrict__ wout,
    float* __restrict__ cout)
{
    constexpr int TX = 64, TY = 64;
    constexpr int SH = TY + 4 * D;          // h-conv rows needed (68, 72, 80)
    constexpr int PITCH = 68;               // floats

    __shared__ __align__(16) float s1[SH][PITCH];

    const int tid = threadIdx.x;            // 0..255
    const int b   = blockIdx.z;
    const int x0  = blockIdx.x * TX;
    const int y0  = blockIdx.y * TY;

    const float* in = cin + b * PLANE;      // 32-bit offset ok (8M max)
    const bool xint = (x0 >= 8) && (x0 + TX + 8 <= IMG_W);
    const int xb4 = x0 >> 2;

    // ============ phase 1: horizontal 5-tap, gmem -> smem ============
    constexpr int ITEMS1 = SH * 16;
    constexpr int IT1 = (ITEMS1 + 255) / 256;
    #pragma unroll
    for (int t = 0; t < IT1; t++) {
        const int i = tid + t * 256;
        if (IT1 * 256 == ITEMS1 || i < ITEMS1) {
            const int rr = i >> 4;
            const int oc = i & 15;
            const int gy = reflect_i(y0 - 2 * D + rr, IMG_H);
            const float* rp = in + gy * IMG_W;
            float4 v;
            if (xint) {
                const float4* rp4 = (const float4*)rp;
                if constexpr (D == 4) {
                    float4 A0 = rp4[xb4 + oc - 2];
                    float4 A1 = rp4[xb4 + oc - 1];
                    float4 A2 = rp4[xb4 + oc    ];
                    float4 A3 = rp4[xb4 + oc + 1];
                    float4 A4 = rp4[xb4 + oc + 2];
                    v.x = 0.0625f * (A0.x + A4.x) + 0.25f * (A1.x + A3.x) + 0.375f * A2.x;
                    v.y = 0.0625f * (A0.y + A4.y) + 0.25f * (A1.y + A3.y) + 0.375f * A2.y;
                    v.z = 0.0625f * (A0.z + A4.z) + 0.25f * (A1.z + A3.z) + 0.375f * A2.z;
                    v.w = 0.0625f * (A0.w + A4.w) + 0.25f * (A1.w + A3.w) + 0.375f * A2.w;
                } else {
                    float4 B0 = rp4[xb4 + oc - 1];
                    float4 B1 = rp4[xb4 + oc    ];
                    float4 B2 = rp4[xb4 + oc + 1];
                    float f[12] = {B0.x, B0.y, B0.z, B0.w,
                                   B1.x, B1.y, B1.z, B1.w,
                                   B2.x, B2.y, B2.z, B2.w};
                    v.x = 0.0625f * (f[4 - 2*D] + f[4 + 2*D]) + 0.25f * (f[4 - D] + f[4 + D]) + 0.375f * f[4];
                    v.y = 0.0625f * (f[5 - 2*D] + f[5 + 2*D]) + 0.25f * (f[5 - D] + f[5 + D]) + 0.375f * f[5];
                    v.z = 0.0625f * (f[6 - 2*D] + f[6 + 2*D]) + 0.25f * (f[6 - D] + f[6 + D]) + 0.375f * f[6];
                    v.w = 0.0625f * (f[7 - 2*D] + f[7 + 2*D]) + 0.25f * (f[7 - D] + f[7 + D]) + 0.375f * f[7];
                }
            } else {
                const int xl = x0 + oc * 4;
                float o[4];
                #pragma unroll
                for (int n = 0; n < 4; n++) {
                    float a0 = rp[reflect_i(xl + n - 2 * D, IMG_W)];
                    float a1 = rp[reflect_i(xl + n -     D, IMG_W)];
                    float a2 = rp[reflect_i(xl + n,         IMG_W)];
                    float a3 = rp[reflect_i(xl + n +     D, IMG_W)];
                    float a4 = rp[reflect_i(xl + n + 2 * D, IMG_W)];
                    o[n] = 0.0625f * (a0 + a4) + 0.25f * (a1 + a3) + 0.375f * a2;
                }
                v = make_float4(o[0], o[1], o[2], o[3]);
            }
            *(float4*)&s1[rr][oc * 4] = v;
        }
    }

    // -------- prefetch center values (independent of smem) --------
    const int col = tid & 15;               // f4 column 0..15
    const int r0  = tid >> 4;               // base row 0..15; items at r0+16k
    const float4* in4 = (const float4*)in;
    int go[4];
    float4 cc[4];
    #pragma unroll
    for (int k = 0; k < 4; k++) {
        go[k] = (y0 + r0 + 16 * k) * W4 + xb4 + col;
        cc[k] = in4[go[k]];
    }

    __syncthreads();

    // ============ phase 2: vertical 5-tap from smem ============
    float4* wo = (float4*)(wout + b * 4 * PLANE);
    float4* co = (float4*)(cout + b * (LAST ? 4 : 1) * PLANE);

    #pragma unroll
    for (int k = 0; k < 4; k++) {
        const int r = r0 + 16 * k;          // tile row; s1 rows r .. r+4D
        float4 a0 = *(const float4*)&s1[r        ][col * 4];
        float4 a1 = *(const float4*)&s1[r +     D][col * 4];
        float4 a2 = *(const float4*)&s1[r + 2 * D][col * 4];
        float4 a3 = *(const float4*)&s1[r + 3 * D][col * 4];
        float4 a4 = *(const float4*)&s1[r + 4 * D][col * 4];
        float4 v;
        v.x = 0.0625f * (a0.x + a4.x) + 0.25f * (a1.x + a3.x) + 0.375f * a2.x;
        v.y = 0.0625f * (a0.y + a4.y) + 0.25f * (a1.y + a3.y) + 0.375f * a2.y;
        v.z = 0.0625f * (a0.z + a4.z) + 0.25f * (a1.z + a3.z) + 0.375f * a2.z;
        v.w = 0.0625f * (a0.w + a4.w) + 0.25f * (a1.w + a3.w) + 0.375f * a2.w;

        float4 w4 = make_float4(cc[k].x - v.x, cc[k].y - v.y,
                                cc[k].z - v.z, cc[k].w - v.w);
        __stcs(&wo[go[k]], w4);             // w: write-once, evict-first
        if constexpr (LAST)
            __stcs(&co[go[k]], v);          // c3: write-once too
        else
            co[go[k]] = v;                  // c_next: re-read by next level
    }
}

extern "C" void kernel_launch(void* const* d_in, const int* in_sizes, int n_in,
                              void* d_out, int out_size)
{
    (void)in_sizes; (void)n_in; (void)out_size;
    const float* x = (const float*)d_in[0];
    float* out = (float*)d_out;

    float *c1, *c2;
    cudaGetSymbolAddress((void**)&c1, g_scratch1);
    cudaGetSymbolAddress((void**)&c2, g_scratch2);

    dim3 block(256, 1, 1);
    dim3 grid(IMG_W / 64, IMG_H / 64, NBATCH);

    // Note: wout indexes with batch stride 4*PLANE internally; cout stride is
    // PLANE for scratch (LAST=false) and 4*PLANE for the final level.
    uwt_level_kernel<1, false><<<grid, block>>>(x,  out + 0L * PLANE, c1);
    uwt_level_kernel<2, false><<<grid, block>>>(c1, out + 1L * PLANE, c2);
    uwt_level_kernel<4, true ><<<grid, block>>>(c2, out + 2L * PLANE,
                                                    out + 3L * PLANE);
}